// round 15
// baseline (speedup 1.0000x reference)
#include <cuda_runtime.h>
#include <cstddef>

#define BB 8
#define MM 8192
#define DD 256
#define HOPS 3

// Scratch (allocation-free __device__ globals)
__device__ float g_o[BB * DD];        // cumulative sum of o_k across hops (u = q + g_o)
__device__ float g_logits[BB * MM];
__device__ float g_pmax[BB * 128];    // per-block softmax partials (128 blocks per b)
__device__ float g_psum[BB * 128];
__device__ float g_bmax[BB];
__device__ float g_binv[BB];
__device__ float g_part[1024 * 1024]; // k_ok per-thread partials: [cta][g][c][4] (4 MB)

// ---------------------------------------------------------------------------
// K0: zero the cumulative o accumulator
// ---------------------------------------------------------------------------
__global__ void k_init() {
    g_o[blockIdx.x * 256 + threadIdx.x] = 0.0f;   // 8 blocks x 256
}

// ---------------------------------------------------------------------------
// K1 (R8 verbatim — measured ~6.5-7 TB/s): logits + per-block softmax stats.
// ---------------------------------------------------------------------------
__global__ void __launch_bounds__(256)
k_logits(const float* __restrict__ ms,
         const float* __restrict__ q,
         const float* __restrict__ gp,
         float* __restrict__ out_logits /* null unless last hop */) {
    const int ROWS = 64;
    int row0 = blockIdx.x * ROWS;
    int b = row0 >> 13;                    // 64 | 8192 -> block never straddles b
    int lane = threadIdx.x & 31;
    int warp = threadIdx.x >> 5;

    __shared__ float su[DD];
    __shared__ float srow[ROWS];
    su[threadIdx.x] = q[b * DD + threadIdx.x] + g_o[b * DD + threadIdx.x];
    __syncthreads();

    float4 ub0 = reinterpret_cast<const float4*>(su)[lane];
    float4 ub1 = reinterpret_cast<const float4*>(su)[lane + 32];

    int r0 = row0 + warp * 8;
#pragma unroll
    for (int i = 0; i < 8; i++) {
        int row = r0 + i;
        const float4* rp = reinterpret_cast<const float4*>(ms + (size_t)row * DD);
        float4 a0 = rp[lane];
        float4 a1 = rp[lane + 32];
        float s = a0.x * ub0.x + a0.y * ub0.y + a0.z * ub0.z + a0.w * ub0.w
                + a1.x * ub1.x + a1.y * ub1.y + a1.z * ub1.z + a1.w * ub1.w;
#pragma unroll
        for (int off = 16; off; off >>= 1)
            s += __shfl_xor_sync(0xffffffffu, s, off);
        if (lane == 0) {
            float v = s * gp[row];
            g_logits[row] = v;
            srow[warp * 8 + i] = v;
            if (out_logits) out_logits[row] = v;
        }
    }
    __syncthreads();

    if (warp == 0) {
        float v0 = srow[lane];
        float v1 = srow[lane + 32];
        float m = fmaxf(v0, v1);
#pragma unroll
        for (int off = 16; off; off >>= 1)
            m = fmaxf(m, __shfl_xor_sync(0xffffffffu, m, off));
        float s = __expf(v0 - m) + __expf(v1 - m);
#pragma unroll
        for (int off = 16; off; off >>= 1)
            s += __shfl_xor_sync(0xffffffffu, s, off);
        if (lane == 0) {
            g_pmax[blockIdx.x] = m;
            g_psum[blockIdx.x] = s;
        }
    }
}

// ---------------------------------------------------------------------------
// K2: merge 128 partial (max,sum) pairs per b -> (bmax, 1/sum). 1 CTA, 8 warps.
// ---------------------------------------------------------------------------
__global__ void k_combine() {
    int b = threadIdx.x >> 5;
    int lane = threadIdx.x & 31;
    float m = -1e30f, s = 0.0f;
#pragma unroll
    for (int i = 0; i < 4; i++) {
        int idx = b * 128 + i * 32 + lane;
        float pm = g_pmax[idx], ps = g_psum[idx];
        float nm = fmaxf(m, pm);
        s = s * __expf(m - nm) + ps * __expf(pm - nm);
        m = nm;
    }
#pragma unroll
    for (int off = 16; off; off >>= 1) {
        float om = __shfl_xor_sync(0xffffffffu, m, off);
        float os = __shfl_xor_sync(0xffffffffu, s, off);
        float nm = fmaxf(m, om);
        s = s * __expf(m - nm) + os * __expf(om - nm);
        m = nm;
    }
    if (lane == 0) {
        g_bmax[b] = m;
        g_binv[b] = 1.0f / s;
    }
}

// ---------------------------------------------------------------------------
// K3: barrier-free, atomic-free streamer.
// Thread (c=tid&63, g=tid>>6) accumulates rows {g+4r+16k} weighted, writes ONE
// float4 partial to g_part. Weights computed per-thread from broadcast cached
// loads (all lanes of a warp share g -> same address). No smem, no syncs.
// ---------------------------------------------------------------------------
__global__ void __launch_bounds__(256)
k_ok(const float* __restrict__ ms, const float* __restrict__ gp) {
    const int CHUNK = 64;
    int row0 = blockIdx.x * CHUNK;
    int b = row0 >> 13;
    int tid = threadIdx.x;
    int c = tid & 63;
    int g = tid >> 6;

    float bm = g_bmax[b];
    float bi = g_binv[b];

    // 16 weights for this thread's rows (broadcast loads, L2-cached)
    float w[16];
#pragma unroll
    for (int k = 0; k < 4; k++) {
#pragma unroll
        for (int r = 0; r < 4; r++) {
            int m = g + r * 4 + k * 16;
            w[k * 4 + r] = __expf(g_logits[row0 + m] - bm) * bi * gp[row0 + m];
        }
    }

    const float4* base4 = reinterpret_cast<const float4*>(ms + (size_t)row0 * DD);
    float4 acc0 = make_float4(0.f, 0.f, 0.f, 0.f);
    float4 acc1 = make_float4(0.f, 0.f, 0.f, 0.f);
#pragma unroll
    for (int k = 0; k < 4; k++) {
        int m0 = g + k * 16;
        float4 a0 = base4[(m0     ) * 64 + c];
        float4 a1 = base4[(m0 +  4) * 64 + c];
        float4 a2 = base4[(m0 +  8) * 64 + c];
        float4 a3 = base4[(m0 + 12) * 64 + c];
        float w0 = w[k * 4 + 0], w1 = w[k * 4 + 1], w2 = w[k * 4 + 2], w3 = w[k * 4 + 3];
        acc0.x = fmaf(w0, a0.x, acc0.x); acc1.x = fmaf(w1, a1.x, acc1.x);
        acc0.y = fmaf(w0, a0.y, acc0.y); acc1.y = fmaf(w1, a1.y, acc1.y);
        acc0.z = fmaf(w0, a0.z, acc0.z); acc1.z = fmaf(w1, a1.z, acc1.z);
        acc0.w = fmaf(w0, a0.w, acc0.w); acc1.w = fmaf(w1, a1.w, acc1.w);
        acc0.x = fmaf(w2, a2.x, acc0.x); acc1.x = fmaf(w3, a3.x, acc1.x);
        acc0.y = fmaf(w2, a2.y, acc0.y); acc1.y = fmaf(w3, a3.y, acc1.y);
        acc0.z = fmaf(w2, a2.z, acc0.z); acc1.z = fmaf(w3, a3.z, acc1.z);
        acc0.w = fmaf(w2, a2.w, acc0.w); acc1.w = fmaf(w3, a3.w, acc1.w);
    }
    acc0.x += acc1.x; acc0.y += acc1.y; acc0.z += acc1.z; acc0.w += acc1.w;

    // g_part layout as float: [cta*1024 + g*256 + c*4 + comp]
    reinterpret_cast<float4*>(g_part)[blockIdx.x * 256 + tid] = acc0;
}

// ---------------------------------------------------------------------------
// K3b: fold 512 partials per (b,d) into g_o. 8 CTAs x 256 threads, coalesced.
// ---------------------------------------------------------------------------
__global__ void __launch_bounds__(256)
k_reduce() {
    int b = blockIdx.x;
    int d = threadIdx.x;
    float s = 0.0f;
#pragma unroll 8
    for (int cta = 0; cta < 128; cta++) {
        int base = (b * 128 + cta) * 1024 + d;
        s += g_part[base] + g_part[base + 256] + g_part[base + 512] + g_part[base + 768];
    }
    g_o[b * 256 + d] += s;
}

// ---------------------------------------------------------------------------
// K4 (last hop only): prob_soft = softmax(logits)
// ---------------------------------------------------------------------------
__global__ void k_prob(float* __restrict__ out_prob) {
    int i = blockIdx.x * 256 + threadIdx.x;
    int b = i >> 13;
    out_prob[i] = __expf(g_logits[i] - g_bmax[b]) * g_binv[b];
}

// ---------------------------------------------------------------------------
extern "C" void kernel_launch(void* const* d_in, const int* in_sizes, int n_in,
                              void* d_out, int out_size) {
    const float* q  = (const float*)d_in[0];   // (8,256)
    const float* gp = (const float*)d_in[1];   // (8,8192)
    const float* ms = (const float*)d_in[2];   // (4,8,8192,256)

    float* out        = (float*)d_out;
    float* out_prob   = out;                   // prob_soft  : first  B*M
    float* out_logits = out + BB * MM;         // prob_logits: second B*M

    const size_t SLICE = (size_t)BB * MM * DD;

    k_init<<<8, 256>>>();

    for (int h = 0; h < HOPS; h++) {
        bool last = (h == HOPS - 1);
        k_logits<<<BB * MM / 64, 256>>>(ms + (size_t)h * SLICE, q, gp,
                                        last ? out_logits : nullptr);
        k_combine<<<1, 256>>>();
        if (!last) {
            // Slice h+1 is read here and again by the next k_logits while it
            // may still be L2-resident — keep this ordering.
            k_ok<<<BB * MM / 64, 256>>>(ms + (size_t)(h + 1) * SLICE, gp);
            k_reduce<<<BB, 256>>>();
        } else {
            k_prob<<<BB * MM / 256, 256>>>(out_prob);
        }
    }
}